// round 14
// baseline (speedup 1.0000x reference)
#include <cuda_runtime.h>

#define IN_F   5
#define D_FC   32
#define D_H    64
#define NG     256      // 4*D_H gate rows
#define T_LEN  512
#define B_TOT  4096
#define NBLK   296      // 148 SMs * 2 blocks, single wave
#define BLOCK  256      // 8 warps: w0-3 (i,g), w4-7 (f,o); lane halves split K
#define CHUNK  16       // x staging chunk (timesteps)
#define NB_MAX 14       // 248 blocks get 14 batches, 48 get 13
#define XPAD   6        // x padded to 6 floats: [x0..x4, 1.0]
#define LOG2E  1.4426950408889634f

// Prescaled fused input projection + prescaled W_hh.
//   g_Wc[r][0..4] = s_r * (W_ih@W0)[r],  g_Wc[r][5] = s_r * bias_comb[r]
//   g_Whh[r][:]   = s_r * W_hh[r][:]
//   s_r = -2*log2e for tanh rows (g: 128..191), -log2e otherwise (sigmoid).
//   sigmoid(a) = rcp(1 + ex2(-log2e*a)),  tanh(a) = 2*rcp(1+ex2(-2log2e*a))-1.
__device__ float g_Wc[NG * XPAD];
__device__ float g_Whh[NG * D_H];

// ---------------------------------------------------------------------------
// Setup: fold fc0 into LSTM input projection, prescale everything.
// ---------------------------------------------------------------------------
__global__ void precompute_kernel(const float* __restrict__ W0,
                                  const float* __restrict__ b0,
                                  const float* __restrict__ W_ih,
                                  const float* __restrict__ b_ih,
                                  const float* __restrict__ b_hh,
                                  const float* __restrict__ W_hh)
{
    int r = blockIdx.x * blockDim.x + threadIdx.x;
    if (r >= NG) return;
    float wc[IN_F] = {0.f, 0.f, 0.f, 0.f, 0.f};
    float bc = b_ih[r] + b_hh[r];
    for (int m = 0; m < D_FC; ++m) {
        float wim = W_ih[r * D_FC + m];
        bc += wim * b0[m];
        #pragma unroll
        for (int k = 0; k < IN_F; ++k)
            wc[k] += wim * W0[m * IN_F + k];
    }
    const float s = (r >= 128 && r < 192) ? (-2.f * LOG2E) : (-LOG2E);
    #pragma unroll
    for (int k = 0; k < IN_F; ++k) g_Wc[r * XPAD + k] = s * wc[k];
    g_Wc[r * XPAD + 5] = s * bc;
    for (int k = 0; k < D_H; ++k)
        g_Whh[r * D_H + k] = s * W_hh[r * D_H + k];
}

// ---------------------------------------------------------------------------
// Packed f32x2 + MUFU helpers
// ---------------------------------------------------------------------------
typedef unsigned long long ull;

__device__ __forceinline__ ull fma2(ull a, ull b, ull c)
{
    ull d;
    asm("fma.rn.f32x2 %0, %1, %2, %3;" : "=l"(d) : "l"(a), "l"(b), "l"(c));
    return d;
}

__device__ __forceinline__ ull add2(ull a, ull b)
{
    ull d;
    asm("add.rn.f32x2 %0, %1, %2;" : "=l"(d) : "l"(a), "l"(b));
    return d;
}

__device__ __forceinline__ float2 u2f2(ull v)
{
    float2 r;
    asm("mov.b64 {%0, %1}, %2;" : "=f"(r.x), "=f"(r.y) : "l"(v));
    return r;
}

__device__ __forceinline__ float ex2_(float x)
{
    float y;
    asm("ex2.approx.ftz.f32 %0, %1;" : "=f"(y) : "f"(x));
    return y;
}

__device__ __forceinline__ float rcp_(float x)
{
    float y;
    asm("rcp.approx.ftz.f32 %0, %1;" : "=f"(y) : "f"(x));
    return y;
}

__device__ __forceinline__ float tanh_(float x)   // true-scale tanh
{
    float e = ex2_(-2.f * LOG2E * x);
    return __fmaf_rn(2.f, rcp_(1.f + e), -1.f);
}

// ---------------------------------------------------------------------------
// Fused persistent LSTM kernel, K-split layout for 4 warps/SMSP.
//   warp 0-3 (half=0): rows (j, j+128)  = (i, g) -> aig = sigmoid(i)*tanh(g)
//   warp 4-7 (half=1): rows (j+64,j+192)= (f, o) -> sf, so
//   j = (warp&3)*16 + (lane&15); lanes 0-15 own h[0:32], 16-31 own h[32:64].
//   K-halves combine via shfl.xor(16), pipelined one batch behind the dot.
// ---------------------------------------------------------------------------
__global__ void __launch_bounds__(BLOCK, 2)
lstm_kernel(const float* __restrict__ x,
            const float* __restrict__ Wo,
            const float* __restrict__ bo,
            float* __restrict__ out)
{
    __shared__ __align__(16) float h_sh[NB_MAX * D_H];              // 3.5 KB
    __shared__ float c_sh[NB_MAX * D_H];                             // 3.5 KB
    __shared__ float aig_sh[NB_MAX * D_H];                           // 3.5 KB
    __shared__ float sf_sh[NB_MAX * D_H];                            // 3.5 KB
    __shared__ float so_sh[NB_MAX * D_H];                            // 3.5 KB
    __shared__ __align__(16) float x_sh[NB_MAX * CHUNK * XPAD + 8];  // 5.3 KB
    __shared__ float wo_sh[D_H];

    const int tid  = threadIdx.x;
    const int bid  = blockIdx.x;
    const int lane = tid & 31;
    const int warp = tid >> 5;
    const int half = warp >> 2;                 // 0:(i,g)  1:(f,o)
    const int j    = (warp & 3) * 16 + (lane & 15);   // hidden unit
    const int kh32 = (lane >> 4) * 32;          // K-half offset
    const int kh0  = (lane < 16);               // this lane stores EPI results

    // batch partition: 248 blocks * 14 + 48 blocks * 13 = 4096
    int nb, b0g;
    if (bid < 248) { nb = 14; b0g = bid * 14; }
    else           { nb = 13; b0g = 3472 + (bid - 248) * 13; }

    // rows owned by this thread
    const int r0 = half ? (j + 64)  : j;          // f : i   (sigmoid rows)
    const int r1 = half ? (j + 192) : (j + 128);  // o : g

    // register-resident prescaled W_hh row K-slices (16 packed pairs each)
    ull w0[16], w1[16];
    {
        const ull* p0 = (const ull*)(g_Whh + r0 * D_H + kh32);
        const ull* p1 = (const ull*)(g_Whh + r1 * D_H + kh32);
        #pragma unroll
        for (int i = 0; i < 16; ++i) { w0[i] = p0[i]; w1[i] = p1[i]; }
    }

    // prescaled input weights: kh0 lanes take pairs {0,1}=(x0,x1),(x2,x3);
    // kh1 lanes take pair {2}=(x4,bias) and a zero pair (reads padded x).
    ull wcA0, wcA1, wcB0, wcB1;
    {
        const ull* a = (const ull*)(g_Wc + r0 * XPAD);  // 24B rows, 8B aligned
        const ull* b = (const ull*)(g_Wc + r1 * XPAD);
        if (kh0) { wcA0 = a[0]; wcA1 = a[1]; wcB0 = b[0]; wcB1 = b[1]; }
        else     { wcA0 = a[2]; wcA1 = 0ull; wcB0 = b[2]; wcB1 = 0ull; }
    }

    // per-half nonlinearity constants for acc1 (vb = mm*rcp(1+ex2(acc1)) + ca)
    const float mm = half ? 1.f : 2.f;
    const float ca = half ? 0.f : -1.f;

    if (tid < D_H) wo_sh[tid] = Wo[tid];
    for (int i = tid; i < NB_MAX * D_H; i += BLOCK) {
        h_sh[i] = 0.f; c_sh[i] = 0.f;
        aig_sh[i] = 0.f; sf_sh[i] = 0.f; so_sh[i] = 0.f;
    }
    for (int i = tid; i < NB_MAX * CHUNK * XPAD + 8; i += BLOCK)
        x_sh[i] = ((i % XPAD) == 5) ? 1.f : 0.f;   // constant-1 bias lane
    __syncthreads();

    for (int t = 0; t < T_LEN; ++t) {
        // ---- stage x chunk (previous chunk fully consumed before this point)
        if ((t & (CHUNK - 1)) == 0) {
            #pragma unroll 1
            for (int i = tid; i < NB_MAX * CHUNK * IN_F; i += BLOCK) {
                int b  = i / (CHUNK * IN_F);
                int rm = i - b * (CHUNK * IN_F);
                int tt = rm / IN_F;
                int k  = rm - tt * IN_F;
                int gb = b0g + b;
                if (gb > B_TOT - 1) gb = B_TOT - 1;   // clamp (data unused)
                x_sh[(b * CHUNK + tt) * XPAD + k] =
                    x[((long long)gb * T_LEN + t + tt) * IN_F + k];
            }
            __syncthreads();
        }

        const int tslot = t & (CHUNK - 1);

        // dot over this lane's K-half, then K-reduce across lane halves.
        // The shfl results are consumed one pipeline stage later (EPI(b)).
        #define DOT(B, A0, A1)                                                 \
        {                                                                      \
            const ulonglong2* hp =                                             \
                (const ulonglong2*)(h_sh + (B) * D_H + kh32);                  \
            const ull* xq =                                                    \
                (const ull*)(x_sh + ((B) * CHUNK + tslot) * XPAD)              \
                + (kh0 ? 0 : 2);                                               \
            ull xv0 = xq[0], xv1 = xq[1];                                      \
            ull a00 = fma2(wcA0, xv0, 0ull);                                   \
            ull a10 = fma2(wcB0, xv0, 0ull);                                   \
            ull a01 = fma2(wcA1, xv1, 0ull);                                   \
            ull a11 = fma2(wcB1, xv1, 0ull);                                   \
            _Pragma("unroll")                                                  \
            for (int i = 0; i < 8; ++i) {                                      \
                ulonglong2 hv = hp[i];         /* 2-group broadcast LDS.128 */ \
                a00 = fma2(w0[2 * i],     hv.x, a00);                          \
                a10 = fma2(w1[2 * i],     hv.x, a10);                          \
                a01 = fma2(w0[2 * i + 1], hv.y, a01);                          \
                a11 = fma2(w1[2 * i + 1], hv.y, a11);                          \
            }                                                                  \
            ull s0_ = add2(a00, a01), s1_ = add2(a10, a11);                    \
            float2 f0 = u2f2(s0_), f1 = u2f2(s1_);                             \
            A0 = f0.x + f0.y;                                                  \
            A1 = f1.x + f1.y;                                                  \
            A0 += __shfl_xor_sync(0xffffffffu, A0, 16);                        \
            A1 += __shfl_xor_sync(0xffffffffu, A1, 16);                        \
        }

        // epilogue (all lanes compute; lane halves hold identical values;
        // kh0 lanes store)
        #define EPI(B, A0, A1)                                                 \
        {                                                                      \
            float e0 = ex2_(A0);                                               \
            float e1 = ex2_(A1);                                               \
            float s0 = rcp_(1.f + e0);          /* sigmoid(i) / sigmoid(f) */  \
            float rr = rcp_(1.f + e1);                                         \
            float vb = __fmaf_rn(mm, rr, ca);   /* tanh(g) / sigmoid(o)   */   \
            if (half == 0) {                                                   \
                if (kh0) aig_sh[(B) * D_H + j] = s0 * vb;                      \
            } else {                                                           \
                if (kh0) { sf_sh[(B) * D_H + j] = s0;                          \
                           so_sh[(B) * D_H + j] = vb; }                        \
            }                                                                  \
        }

        // ---- phase 1, pipelined: EPI(b-1) interleaves with DOT(b)
        float p0, p1;
        DOT(0, p0, p1);
        #pragma unroll 1
        for (int b = 1; b < nb; ++b) {
            float n0, n1;
            DOT(b, n0, n1);
            EPI(b - 1, p0, p1);
            p0 = n0; p1 = n1;
        }
        EPI(nb - 1, p0, p1);
        #undef DOT
        #undef EPI
        __syncthreads();

        // ---- phase 2: state update (1 tanh per unit, c in smem)
        #pragma unroll
        for (int s = 0; s < (NB_MAX * D_H + BLOCK - 1) / BLOCK; ++s) {
            int u = tid + BLOCK * s;
            if (u < nb * D_H) {
                float a  = aig_sh[u];
                float sf = sf_sh[u];
                float so = so_sh[u];
                float cc = __fmaf_rn(sf, c_sh[u], a);
                c_sh[u] = cc;
                h_sh[u] = so * tanh_(cc);
            }
        }
        __syncthreads();
    }

    // ---- output: out[b] = Wo @ h_last + bo
    if (tid < nb) {
        float acc = bo[0];
        #pragma unroll
        for (int k = 0; k < D_H; ++k)
            acc = __fmaf_rn(wo_sh[k], h_sh[tid * D_H + k], acc);
        out[b0g + tid] = acc;
    }
}

// ---------------------------------------------------------------------------
// Harness entry. Inputs (metadata order):
//   0:x 1:W0 2:b0 3:W_ih 4:W_hh 5:b_ih 6:b_hh 7:Wo 8:bo ; out: float[4096]
// ---------------------------------------------------------------------------
extern "C" void kernel_launch(void* const* d_in, const int* in_sizes, int n_in,
                              void* d_out, int out_size)
{
    (void)in_sizes; (void)n_in; (void)out_size;
    const float* x    = (const float*)d_in[0];
    const float* W0   = (const float*)d_in[1];
    const float* b0   = (const float*)d_in[2];
    const float* W_ih = (const float*)d_in[3];
    const float* W_hh = (const float*)d_in[4];
    const float* b_ih = (const float*)d_in[5];
    const float* b_hh = (const float*)d_in[6];
    const float* Wo   = (const float*)d_in[7];
    const float* bo   = (const float*)d_in[8];

    precompute_kernel<<<1, NG>>>(W0, b0, W_ih, b_ih, b_hh, W_hh);
    lstm_kernel<<<NBLK, BLOCK>>>(x, Wo, bo, (float*)d_out);
}

// round 16
// speedup vs baseline: 1.0086x; 1.0086x over previous
#include <cuda_runtime.h>

#define IN_F   5
#define D_FC   32
#define D_H    64
#define NG     256      // 4*D_H gate rows
#define T_LEN  512
#define B_TOT  4096
#define NBLK   444      // 148 SMs * 3 blocks, single wave
#define BLOCK  128      // 4 warps; thread owns unit j = warp*16 + (lane&15)
#define CHUNK  16       // x staging chunk (timesteps)
#define NB_MAX 10       // 100 blocks get 10 batches, 344 get 9
#define XPAD   6        // x padded to 6 floats: [x0..x4, 1.0]
#define LOG2E  1.4426950408889634f

// Prescaled fused input projection + prescaled W_hh.
//   g_Wc[r][0..4] = s_r * (W_ih@W0)[r],  g_Wc[r][5] = s_r * bias_comb[r]
//   g_Whh[r][:]   = s_r * W_hh[r][:]
//   s_r = -2*log2e for tanh rows (g: 128..191), -log2e otherwise (sigmoid).
//   sigmoid(a) = rcp(1 + ex2(-log2e*a)),  tanh(a) = 2*rcp(1+ex2(-2log2e*a))-1.
__device__ float g_Wc[NG * XPAD];
__device__ float g_Whh[NG * D_H];

// ---------------------------------------------------------------------------
// Setup: fold fc0 into LSTM input projection, prescale everything.
// ---------------------------------------------------------------------------
__global__ void precompute_kernel(const float* __restrict__ W0,
                                  const float* __restrict__ b0,
                                  const float* __restrict__ W_ih,
                                  const float* __restrict__ b_ih,
                                  const float* __restrict__ b_hh,
                                  const float* __restrict__ W_hh)
{
    int r = blockIdx.x * blockDim.x + threadIdx.x;
    if (r >= NG) return;
    float wc[IN_F] = {0.f, 0.f, 0.f, 0.f, 0.f};
    float bc = b_ih[r] + b_hh[r];
    for (int m = 0; m < D_FC; ++m) {
        float wim = W_ih[r * D_FC + m];
        bc += wim * b0[m];
        #pragma unroll
        for (int k = 0; k < IN_F; ++k)
            wc[k] += wim * W0[m * IN_F + k];
    }
    const float s = (r >= 128 && r < 192) ? (-2.f * LOG2E) : (-LOG2E);
    #pragma unroll
    for (int k = 0; k < IN_F; ++k) g_Wc[r * XPAD + k] = s * wc[k];
    g_Wc[r * XPAD + 5] = s * bc;
    for (int k = 0; k < D_H; ++k)
        g_Whh[r * D_H + k] = s * W_hh[r * D_H + k];
}

// ---------------------------------------------------------------------------
// Packed f32x2 + MUFU helpers
// ---------------------------------------------------------------------------
typedef unsigned long long ull;

__device__ __forceinline__ ull fma2(ull a, ull b, ull c)
{
    ull d;
    asm("fma.rn.f32x2 %0, %1, %2, %3;" : "=l"(d) : "l"(a), "l"(b), "l"(c));
    return d;
}

__device__ __forceinline__ float2 u2f2(ull v)
{
    float2 r;
    asm("mov.b64 {%0, %1}, %2;" : "=f"(r.x), "=f"(r.y) : "l"(v));
    return r;
}

__device__ __forceinline__ float ex2_(float x)
{
    float y;
    asm("ex2.approx.ftz.f32 %0, %1;" : "=f"(y) : "f"(x));
    return y;
}

__device__ __forceinline__ float rcp_(float x)
{
    float y;
    asm("rcp.approx.ftz.f32 %0, %1;" : "=f"(y) : "f"(x));
    return y;
}

__device__ __forceinline__ float tanh_(float x)   // true-scale tanh
{
    float e = ex2_(-2.f * LOG2E * x);
    return __fmaf_rn(2.f, rcp_(1.f + e), -1.f);
}

// ---------------------------------------------------------------------------
// Fused persistent LSTM kernel — one thread owns a whole LSTM unit.
//   unit j = (warp)*16 + (lane&15); lanes 0-15 own K[0:32], 16-31 K[32:64].
//   Thread holds prescaled W_hh rows (i,f,g,o) for unit j over its K-half:
//   4 x 16 packed pairs = 128 regs. After 4 dots + shfl.xor(16) reductions,
//   the thread updates c (private smem) and writes h (ping-pong smem).
//   ONE __syncthreads per step; no phase 2; no gate arrays.
// ---------------------------------------------------------------------------
__global__ void __launch_bounds__(BLOCK, 3)
lstm_kernel(const float* __restrict__ x,
            const float* __restrict__ Wo,
            const float* __restrict__ bo,
            float* __restrict__ out)
{
    __shared__ __align__(16) float h2[2][NB_MAX * D_H];             // 2 x 2.5 KB
    __shared__ float c_sh[NB_MAX * D_H];                             // 2.5 KB
    __shared__ __align__(16) float x_sh[NB_MAX * CHUNK * XPAD + 8];  // 3.8 KB
    __shared__ float wo_sh[D_H];

    const int tid  = threadIdx.x;
    const int bid  = blockIdx.x;
    const int lane = tid & 31;
    const int warp = tid >> 5;
    const int j    = warp * 16 + (lane & 15);   // hidden unit (0..63)
    const int kh32 = (lane >> 4) * 32;          // K-half offset
    const int kh0  = (lane < 16);               // lanes that commit results
    const int xoff = kh0 ? 0 : 2;               // x pair offset for this half

    // batch partition: 100 blocks * 10 + 344 blocks * 9 = 4096
    int nb, b0g;
    if (bid < 100) { nb = 10; b0g = bid * 10; }
    else           { nb = 9;  b0g = 1000 + (bid - 100) * 9; }

    // gate rows of unit j
    const int ri = j, rf = j + 64, rg_ = j + 128, ro = j + 192;

    // register-resident prescaled W_hh K-half slices: 4 rows x 16 pairs
    ull w0[16], w1[16], w2[16], w3[16];
    {
        const ull* p0 = (const ull*)(g_Whh + ri  * D_H + kh32);
        const ull* p1 = (const ull*)(g_Whh + rf  * D_H + kh32);
        const ull* p2 = (const ull*)(g_Whh + rg_ * D_H + kh32);
        const ull* p3 = (const ull*)(g_Whh + ro  * D_H + kh32);
        #pragma unroll
        for (int i = 0; i < 16; ++i) {
            w0[i] = p0[i]; w1[i] = p1[i]; w2[i] = p2[i]; w3[i] = p3[i];
        }
    }

    // prescaled input weights: kh0 lanes take pairs {0,1} = (x0,x1),(x2,x3);
    // kh1 lanes take pair {2} = (x4, bias*1) and a zero pair.
    ull wx0[2], wx1[2], wx2[2], wx3[2];
    {
        const ull* a = (const ull*)(g_Wc + ri  * XPAD);
        const ull* b = (const ull*)(g_Wc + rf  * XPAD);
        const ull* c = (const ull*)(g_Wc + rg_ * XPAD);
        const ull* d = (const ull*)(g_Wc + ro  * XPAD);
        if (kh0) {
            wx0[0] = a[0]; wx0[1] = a[1];
            wx1[0] = b[0]; wx1[1] = b[1];
            wx2[0] = c[0]; wx2[1] = c[1];
            wx3[0] = d[0]; wx3[1] = d[1];
        } else {
            wx0[0] = a[2]; wx0[1] = 0ull;
            wx1[0] = b[2]; wx1[1] = 0ull;
            wx2[0] = c[2]; wx2[1] = 0ull;
            wx3[0] = d[2]; wx3[1] = 0ull;
        }
    }

    if (tid < D_H) wo_sh[tid] = Wo[tid];
    for (int i = tid; i < NB_MAX * D_H; i += BLOCK) {
        h2[0][i] = 0.f; h2[1][i] = 0.f; c_sh[i] = 0.f;
    }
    for (int i = tid; i < NB_MAX * CHUNK * XPAD + 8; i += BLOCK)
        x_sh[i] = ((i % XPAD) == 5) ? 1.f : 0.f;   // constant-1 bias lane
    __syncthreads();

    for (int t = 0; t < T_LEN; ++t) {
        // ---- stage x chunk (previous chunk fully consumed: end-of-step
        //      barrier of t-1 already passed)
        if ((t & (CHUNK - 1)) == 0) {
            #pragma unroll 1
            for (int i = tid; i < NB_MAX * CHUNK * IN_F; i += BLOCK) {
                int b  = i / (CHUNK * IN_F);
                int rm = i - b * (CHUNK * IN_F);
                int tt = rm / IN_F;
                int k  = rm - tt * IN_F;
                int gb = b0g + b;
                if (gb > B_TOT - 1) gb = B_TOT - 1;   // clamp (data unused)
                x_sh[(b * CHUNK + tt) * XPAD + k] =
                    x[((long long)gb * T_LEN + t + tt) * IN_F + k];
            }
            __syncthreads();
        }

        const int tslot = t & (CHUNK - 1);
        const float* hold = h2[t & 1];
        float*       hnew = h2[(t & 1) ^ 1];

        // 4 gate dots over this lane's K-half; K-reduce via shfl.xor(16).
        // Results consumed one pipeline stage later (EPI).
        #define DOT(B, A0, A1, A2, A3)                                         \
        {                                                                      \
            const ulonglong2* hp =                                             \
                (const ulonglong2*)(hold + (B) * D_H + kh32);                  \
            const ull* xq =                                                    \
                (const ull*)(x_sh + ((B) * CHUNK + tslot) * XPAD) + xoff;      \
            ull xv0 = xq[0], xv1 = xq[1];                                      \
            ull a0 = fma2(wx0[0], xv0, 0ull);                                  \
            ull a1 = fma2(wx1[0], xv0, 0ull);                                  \
            ull a2 = fma2(wx2[0], xv0, 0ull);                                  \
            ull a3 = fma2(wx3[0], xv0, 0ull);                                  \
            a0 = fma2(wx0[1], xv1, a0);                                        \
            a1 = fma2(wx1[1], xv1, a1);                                        \
            a2 = fma2(wx2[1], xv1, a2);                                        \
            a3 = fma2(wx3[1], xv1, a3);                                        \
            _Pragma("unroll")                                                  \
            for (int i = 0; i < 8; ++i) {                                      \
                ulonglong2 hv = hp[i];       /* 2-group broadcast LDS.128 */   \
                a0 = fma2(w0[2 * i], hv.x, a0);                                \
                a1 = fma2(w1[2 * i], hv.x, a1);                                \
                a2 = fma2(w2[2 * i], hv.x, a2);                                \
                a3 = fma2(w3[2 * i], hv.x, a3);                                \
                a0 = fma2(w0[2 * i + 1], hv.y, a0);                            \
                a1 = fma2(w1[2 * i + 1], hv.y, a1);                            \
                a2 = fma2(w2[2 * i + 1], hv.y, a2);                            \
                a3 = fma2(w3[2 * i + 1], hv.y, a3);                            \
            }                                                                  \
            float2 f0 = u2f2(a0), f1 = u2f2(a1), f2 = u2f2(a2), f3 = u2f2(a3); \
            A0 = f0.x + f0.y;  A1 = f1.x + f1.y;                               \
            A2 = f2.x + f2.y;  A3 = f3.x + f3.y;                               \
            A0 += __shfl_xor_sync(0xffffffffu, A0, 16);                        \
            A1 += __shfl_xor_sync(0xffffffffu, A1, 16);                        \
            A2 += __shfl_xor_sync(0xffffffffu, A2, 16);                        \
            A3 += __shfl_xor_sync(0xffffffffu, A3, 16);                        \
        }

        // full cell update for unit j, batch B (kh0 lanes commit)
        #define EPI(B, A0, A1, A2, A3)                                         \
        if (kh0) {                                                             \
            float si = rcp_(1.f + ex2_(A0));                  /* sigmoid(i) */ \
            float sf = rcp_(1.f + ex2_(A1));                  /* sigmoid(f) */ \
            float tg = __fmaf_rn(2.f, rcp_(1.f + ex2_(A2)), -1.f); /* tanh  */ \
            float so = rcp_(1.f + ex2_(A3));                  /* sigmoid(o) */ \
            float cold = c_sh[(B) * D_H + j];                                  \
            float cc = __fmaf_rn(sf, cold, si * tg);                           \
            c_sh[(B) * D_H + j] = cc;                                          \
            hnew[(B) * D_H + j] = so * tanh_(cc);                              \
        }

        // ---- pipelined batch loop: EPI(b-1) overlaps DOT(b)
        float p0, p1, p2, p3;
        DOT(0, p0, p1, p2, p3);
        #pragma unroll 1
        for (int b = 1; b < nb; ++b) {
            float n0, n1, n2, n3;
            DOT(b, n0, n1, n2, n3);
            EPI(b - 1, p0, p1, p2, p3);
            p0 = n0; p1 = n1; p2 = n2; p3 = n3;
        }
        EPI(nb - 1, p0, p1, p2, p3);
        #undef DOT
        #undef EPI

        __syncthreads();   // hnew complete before next step reads it
    }

    // ---- output: out[b] = Wo @ h_last + bo  (final h lives in h2[0])
    if (tid < nb) {
        float acc = bo[0];
        #pragma unroll
        for (int k = 0; k < D_H; ++k)
            acc = __fmaf_rn(wo_sh[k], h2[0][tid * D_H + k], acc);
        out[b0g + tid] = acc;
    }
}

// ---------------------------------------------------------------------------
// Harness entry. Inputs (metadata order):
//   0:x 1:W0 2:b0 3:W_ih 4:W_hh 5:b_ih 6:b_hh 7:Wo 8:bo ; out: float[4096]
// ---------------------------------------------------------------------------
extern "C" void kernel_launch(void* const* d_in, const int* in_sizes, int n_in,
                              void* d_out, int out_size)
{
    (void)in_sizes; (void)n_in; (void)out_size;
    const float* x    = (const float*)d_in[0];
    const float* W0   = (const float*)d_in[1];
    const float* b0   = (const float*)d_in[2];
    const float* W_ih = (const float*)d_in[3];
    const float* W_hh = (const float*)d_in[4];
    const float* b_ih = (const float*)d_in[5];
    const float* b_hh = (const float*)d_in[6];
    const float* Wo   = (const float*)d_in[7];
    const float* bo   = (const float*)d_in[8];

    precompute_kernel<<<1, NG>>>(W0, b0, W_ih, b_ih, b_hh, W_hh);
    lstm_kernel<<<NBLK, BLOCK>>>(x, Wo, bo, (float*)d_out);
}

// round 17
// speedup vs baseline: 3.9433x; 3.9097x over previous
#include <cuda_runtime.h>
#include <cstdint>

#define IN_F   5
#define D_FC   32
#define D_H    64
#define NG     256      // 4*D_H gate rows
#define T_LEN  512
#define B_TOT  4096
#define BT     16       // batches per block (one m16 tile)
#define NBLK   (B_TOT / BT)   // 256 blocks, 2 resident per SM
#define BLOCK  256      // 8 warps; warp w owns interleaved gate cols [32w,32w+32)
#define HS     76       // h_sh row stride in floats (conflict-free A loads)
#define XPAD   6
#define LOG2E  1.4426950408889634f

// Prescaled fused input projection + prescaled W_hh (by old row index).
//   g_Wc[r][0..4] = s_r * (W_ih@W0)[r],  g_Wc[r][5] = s_r * bias_comb[r]
//   g_Whh[r][:]   = s_r * W_hh[r][:]
//   s_r = -2*log2e for tanh rows (g: 128..191), -log2e otherwise.
//   sigmoid(a)=rcp(1+ex2(a_scaled)),  tanh(a)=2*rcp(1+ex2(a_scaled))-1.
__device__ float g_Wc[NG * XPAD];
__device__ float g_Whh[NG * D_H];

__global__ void precompute_kernel(const float* __restrict__ W0,
                                  const float* __restrict__ b0,
                                  const float* __restrict__ W_ih,
                                  const float* __restrict__ b_ih,
                                  const float* __restrict__ b_hh,
                                  const float* __restrict__ W_hh)
{
    int r = blockIdx.x * blockDim.x + threadIdx.x;
    if (r >= NG) return;
    float wc[IN_F] = {0.f, 0.f, 0.f, 0.f, 0.f};
    float bc = b_ih[r] + b_hh[r];
    for (int m = 0; m < D_FC; ++m) {
        float wim = W_ih[r * D_FC + m];
        bc += wim * b0[m];
        #pragma unroll
        for (int k = 0; k < IN_F; ++k)
            wc[k] += wim * W0[m * IN_F + k];
    }
    const float s = (r >= 128 && r < 192) ? (-2.f * LOG2E) : (-LOG2E);
    #pragma unroll
    for (int k = 0; k < IN_F; ++k) g_Wc[r * XPAD + k] = s * wc[k];
    g_Wc[r * XPAD + 5] = s * bc;
    for (int k = 0; k < D_H; ++k)
        g_Whh[r * D_H + k] = s * W_hh[r * D_H + k];
}

// ---------------------------------------------------------------------------
// helpers
// ---------------------------------------------------------------------------
__device__ __forceinline__ float ex2_(float x)
{
    float y;
    asm("ex2.approx.ftz.f32 %0, %1;" : "=f"(y) : "f"(x));
    return y;
}

__device__ __forceinline__ float rcp_(float x)
{
    float y;
    asm("rcp.approx.ftz.f32 %0, %1;" : "=f"(y) : "f"(x));
    return y;
}

__device__ __forceinline__ float tanh_(float x)   // true-scale tanh
{
    float e = ex2_(-2.f * LOG2E * x);
    return __fmaf_rn(2.f, rcp_(1.f + e), -1.f);
}

__device__ __forceinline__ uint32_t f2tf(float f)  // round-to-nearest tf32
{
    uint32_t u;
    asm("cvt.rna.tf32.f32 %0, %1;" : "=r"(u) : "f"(f));
    return u;
}

__device__ __forceinline__ void mma_tf32(float& c0, float& c1, float& c2, float& c3,
                                         uint32_t a0, uint32_t a1, uint32_t a2, uint32_t a3,
                                         uint32_t b0, uint32_t b1)
{
    asm("mma.sync.aligned.m16n8k8.row.col.f32.tf32.tf32.f32 "
        "{%0,%1,%2,%3}, {%4,%5,%6,%7}, {%8,%9}, {%0,%1,%2,%3};"
        : "+f"(c0), "+f"(c1), "+f"(c2), "+f"(c3)
        : "r"(a0), "r"(a1), "r"(a2), "r"(a3), "r"(b0), "r"(b1));
}

// ---------------------------------------------------------------------------
// Tensor-core persistent LSTM.
//   gates GEMM per step: D[16, 256] = A[16, 72] x B[72, 256]
//     A = [h(t) | x(t),1 | 0,0] per batch row (tf32-rounded in smem, stride 76)
//     B = prescaled weights, gate cols interleaved: col 4j+g, g in {i,f,g,o}
//   Warp w: 4 n-tiles (cols 32w..32w+31) x 9 k-tiles; B frags in 72 regs.
//   Epilogue: lane pair (l, l^1) holds (i,f)/(g,o) of one unit; 2x shfl.xor(1)
//   completes the cell update in registers. c lives in regs. 1 barrier/step.
// ---------------------------------------------------------------------------
__global__ void __launch_bounds__(BLOCK, 2)
lstm_kernel(const float* __restrict__ x,
            const float* __restrict__ Wo,
            const float* __restrict__ bo,
            float* __restrict__ out)
{
    __shared__ __align__(16) float h2[2][BT * HS];   // 2 x 4864 B

    const int tid  = threadIdx.x;
    const int lane = tid & 31;
    const int w    = tid >> 5;
    const int b0g  = blockIdx.x * BT;

    const int bA  = lane >> 2;        // A-fragment row (batch 0..7; +8 pair)
    const int odd = lane & 1;         // 0: (i,f) cols   1: (g,o) cols
    const int un  = (lane >> 1) & 1;  // unit-within-tile select

    // ---- B fragments: weights resident in registers for the whole kernel
    uint32_t bf[4][9][2];
    #pragma unroll
    for (int nt = 0; nt < 4; ++nt)
        #pragma unroll
        for (int kt = 0; kt < 9; ++kt)
            #pragma unroll
            for (int hfi = 0; hfi < 2; ++hfi) {
                int k = 8 * kt + (lane & 3) + 4 * hfi;
                int n = 32 * w + 8 * nt + (lane >> 2);   // interleaved col
                int j = n >> 2, g = n & 3;
                int old = g * 64 + j;                    // original gate row
                float v = 0.f;
                if (k < 64)      v = g_Whh[old * D_H + k];
                else if (k < 70) v = g_Wc[old * XPAD + (k - 64)];
                bf[nt][kt][hfi] = f2tf(v);
            }

    // ---- init smem (h = 0, x lanes staged below, pads = 0)
    for (int i = tid; i < BT * HS; i += BLOCK) { h2[0][i] = 0.f; h2[1][i] = 0.f; }
    __syncthreads();
    if (tid < BT * 6) {
        int b = tid / 6, q = tid % 6;
        float v = (q < 5) ? x[(size_t)(b0g + b) * T_LEN * IN_F + q] : 1.f;
        h2[0][b * HS + 64 + q] = __uint_as_float(f2tf(v));
    }
    __syncthreads();

    float creg[4] = {0.f, 0.f, 0.f, 0.f};     // cell state, unit (w,nt,un), batch bA(+8*odd)
    const float m0  = odd ? 2.f : 1.f;         // tanh-vs-sigmoid selector for cols 0,2
    const float a0c = odd ? -1.f : 0.f;

    for (int t = 0; t < T_LEN; ++t) {
        const float* cur = h2[t & 1];
        float*       nxt = h2[(t & 1) ^ 1];

        // prefetch x(t+1) early — LDG latency hides under the mma work
        float xv = 0.f; int xb = 0, xq = 0;
        if (tid < BT * 6) {
            xb = tid / 6; xq = tid % 6;
            xv = (xq < 5)
               ? ((t + 1 < T_LEN)
                   ? x[(size_t)(b0g + xb) * T_LEN * IN_F + (t + 1) * IN_F + xq]
                   : 0.f)
               : 1.f;
        }

        // ---- GEMM: 9 k-tiles x 4 n-tiles of m16n8k8
        float C[4][4];
        #pragma unroll
        for (int nt = 0; nt < 4; ++nt) {
            C[nt][0] = 0.f; C[nt][1] = 0.f; C[nt][2] = 0.f; C[nt][3] = 0.f;
        }
        #pragma unroll
        for (int kt = 0; kt < 9; ++kt) {
            int c0i = 8 * kt + (lane & 3);
            uint32_t a0 = __float_as_uint(cur[bA * HS + c0i]);
            uint32_t a1 = __float_as_uint(cur[(bA + 8) * HS + c0i]);
            uint32_t a2 = __float_as_uint(cur[bA * HS + c0i + 4]);
            uint32_t a3 = __float_as_uint(cur[(bA + 8) * HS + c0i + 4]);
            #pragma unroll
            for (int nt = 0; nt < 4; ++nt)
                mma_tf32(C[nt][0], C[nt][1], C[nt][2], C[nt][3],
                         a0, a1, a2, a3, bf[nt][kt][0], bf[nt][kt][1]);
        }

        // ---- epilogue: per n-tile, full cell update via lane-pair exchange
        #pragma unroll
        for (int nt = 0; nt < 4; ++nt) {
            // pre-activations are prescaled: sigmoid = rcp(1+ex2(.)),
            // tanh = 2*rcp(1+ex2(.)) - 1 (cols 0,2 on odd lanes are g-rows)
            float r0 = rcp_(1.f + ex2_(C[nt][0]));
            float r1 = rcp_(1.f + ex2_(C[nt][1]));
            float r2 = rcp_(1.f + ex2_(C[nt][2]));
            float r3 = rcp_(1.f + ex2_(C[nt][3]));
            float g0 = __fmaf_rn(m0, r0, a0c);   // even: sig(i,bA) ; odd: tanh(g,bA)
            float g1 = r1;                        // even: sig(f,bA) ; odd: sig(o,bA)
            float g2 = __fmaf_rn(m0, r2, a0c);   // even: sig(i,bB) ; odd: tanh(g,bB)
            float g3 = r3;                        // even: sig(f,bB) ; odd: sig(o,bB)

            // exchange: even keeps row bA (needs g,o of bA from odd);
            //           odd keeps row bB = bA+8 (needs i,f of bB from even)
            float sA = odd ? g0 : g2;
            float sB = odd ? g1 : g3;
            float xA = __shfl_xor_sync(0xffffffffu, sA, 1);
            float xB = __shfl_xor_sync(0xffffffffu, sB, 1);
            float ii = odd ? xA : g0;
            float ff = odd ? xB : g1;
            float gg = odd ? g2 : xA;
            float oo = odd ? g3 : xB;

            float cc = __fmaf_rn(ff, creg[nt], ii * gg);
            creg[nt] = cc;
            float hh = oo * tanh_(cc);

            int b = bA + (odd ? 8 : 0);
            int u = 8 * w + 2 * nt + un;
            nxt[b * HS + u] = __uint_as_float(f2tf(hh));
        }

        // stage x(t+1) into the next buffer
        if (tid < BT * 6)
            nxt[xb * HS + 64 + xq] = __uint_as_float(f2tf(xv));

        __syncthreads();
    }

    // ---- output: out[b] = Wo @ h_last + bo   (h_last in h2[0] after 512 steps)
    if (tid < BT) {
        float acc = bo[0];
        #pragma unroll
        for (int k = 0; k < D_H; ++k)
            acc = __fmaf_rn(Wo[k], h2[0][tid * HS + k], acc);
        out[b0g + tid] = acc;
    }
}

// ---------------------------------------------------------------------------
// Harness entry. Inputs (metadata order):
//   0:x 1:W0 2:b0 3:W_ih 4:W_hh 5:b_ih 6:b_hh 7:Wo 8:bo ; out: float[4096]
// ---------------------------------------------------------------------------
extern "C" void kernel_launch(void* const* d_in, const int* in_sizes, int n_in,
                              void* d_out, int out_size)
{
    (void)in_sizes; (void)n_in; (void)out_size;
    const float* x    = (const float*)d_in[0];
    const float* W0   = (const float*)d_in[1];
    const float* b0   = (const float*)d_in[2];
    const float* W_ih = (const float*)d_in[3];
    const float* W_hh = (const float*)d_in[4];
    const float* b_ih = (const float*)d_in[5];
    const float* b_hh = (const float*)d_in[6];
    const float* Wo   = (const float*)d_in[7];
    const float* bo   = (const float*)d_in[8];

    precompute_kernel<<<1, NG>>>(W0, b0, W_ih, b_ih, b_hh, W_hh);
    lstm_kernel<<<NBLK, BLOCK>>>(x, Wo, bo, (float*)d_out);
}